// round 7
// baseline (speedup 1.0000x reference)
#include <cuda_runtime.h>
#include <cuda_fp16.h>
#include <cstdint>

#define Bn 64
#define Hn 256
#define Sn 4096

__device__ __half g_Wh[Hn * 512];
__device__ float g_scores[Bn * Sn];
__device__ float g_bias[Bn * Hn];

// ---- smem geometry (bytes) ----
// BK=64: W tile 256h x 64k fp16 (144B padded rows), X tile 64k x 64s fp16.
#define W_STRIDE 144       // 64 fp16 (128B) + 16B pad -> conflict-free ldmatrix
#define X_STRIDE 144
#define OFF_W 0
#define OFF_X 36864        // 256*144
#define STAGE 46080        // 36864 + 64*144
#define SMEM_SZ (2 * STAGE)

// ---------------- PTX helpers (baseline ISA only) ----------------
__device__ __forceinline__ uint32_t smem_u32(const void* p) {
    uint32_t a;
    asm("{ .reg .u64 t; cvta.to.shared.u64 t, %1; cvt.u32.u64 %0, t; }" : "=r"(a) : "l"(p));
    return a;
}
__device__ __forceinline__ void ldsm_x4(uint32_t* r, uint32_t addr) {
    asm volatile("ldmatrix.sync.aligned.m8n8.x4.shared.b16 {%0,%1,%2,%3}, [%4];"
                 : "=r"(r[0]), "=r"(r[1]), "=r"(r[2]), "=r"(r[3]) : "r"(addr));
}
__device__ __forceinline__ void ldsm_x4_t(uint32_t* r, uint32_t addr) {
    asm volatile("ldmatrix.sync.aligned.m8n8.x4.trans.shared.b16 {%0,%1,%2,%3}, [%4];"
                 : "=r"(r[0]), "=r"(r[1]), "=r"(r[2]), "=r"(r[3]) : "r"(addr));
}
__device__ __forceinline__ void mma_f16(float (&d)[4], const uint32_t (&a)[4],
                                        const uint32_t (&b)[2]) {
    asm volatile(
        "mma.sync.aligned.m16n8k16.row.col.f32.f16.f16.f32 "
        "{%0,%1,%2,%3}, {%4,%5,%6,%7}, {%8,%9}, {%0,%1,%2,%3};"
        : "+f"(d[0]), "+f"(d[1]), "+f"(d[2]), "+f"(d[3])
        : "r"(a[0]), "r"(a[1]), "r"(a[2]), "r"(a[3]), "r"(b[0]), "r"(b[1]));
}
#define CP_ASYNC16(s, g) \
    asm volatile("cp.async.cg.shared.global [%0], [%1], 16;" :: "r"(s), "l"(g))
#define CP_COMMIT() asm volatile("cp.async.commit_group;" ::: "memory")
#define CP_WAIT0()  asm volatile("cp.async.wait_group 0;" ::: "memory")

__device__ __forceinline__ float tanh_acc(float x) {
    float z = x * 2.885390082f;           // 2*log2(e)*x
    float e; asm("ex2.approx.f32 %0, %1;" : "=f"(e) : "f"(z));
    float r; asm("rcp.approx.f32 %0, %1;" : "=f"(r) : "f"(e + 1.0f));
    return fmaf(-2.0f, r, 1.0f);          // 1 - 2/(e^{2x}+1)
}

// 8 floats -> 8 fp16 (one uint4)
__device__ __forceinline__ uint4 cvt8h(float4 a, float4 b) {
    __half2 p0 = __floats2half2_rn(a.x, a.y);
    __half2 p1 = __floats2half2_rn(a.z, a.w);
    __half2 p2 = __floats2half2_rn(b.x, b.y);
    __half2 p3 = __floats2half2_rn(b.z, b.w);
    return make_uint4(*(uint32_t*)&p0, *(uint32_t*)&p1,
                      *(uint32_t*)&p2, *(uint32_t*)&p3);
}

// ---------------------------------------------------------------------------
__global__ void convert_w_kernel(const float* __restrict__ W,
                                 __half* __restrict__ wh) {
    int idx = blockIdx.x * 256 + threadIdx.x;  // 0..32767 float4 units
    int h = idx >> 7, c4 = idx & 127;
    float4 w = *(const float4*)(W + (size_t)h * 768 + c4 * 4);
    __half2 h01 = __floats2half2_rn(w.x, w.y);
    __half2 h23 = __floats2half2_rn(w.z, w.w);
    uint2 hh = make_uint2(*(uint32_t*)&h01, *(uint32_t*)&h23);
    *(uint2*)(wh + (size_t)h * 512 + c4 * 4) = hh;
}

// bias[b,h] = W3[h,:] . dh[b,:]  (fp32, exact path)
__global__ void bias_kernel(const float* __restrict__ W,
                            const float* __restrict__ dh,
                            float* __restrict__ bias) {
    int b = blockIdx.x;
    int tid = threadIdx.x;
    __shared__ float sh[Hn];
    if (tid < Hn) sh[tid] = dh[b * Hn + tid];
    __syncthreads();
    int h = tid >> 2, q = tid & 3;
    const float4* Wr = (const float4*)(W + (size_t)h * 768 + 512 + q * 64);
    const float4* sr = (const float4*)(sh + q * 64);
    float a0 = 0.f, a1 = 0.f, a2 = 0.f, a3 = 0.f;
#pragma unroll
    for (int j = 0; j < 16; j++) {
        float4 w4 = __ldg(&Wr[j]); float4 s4 = sr[j];
        a0 = fmaf(w4.x, s4.x, a0); a1 = fmaf(w4.y, s4.y, a1);
        a2 = fmaf(w4.z, s4.z, a2); a3 = fmaf(w4.w, s4.w, a3);
    }
    float r = (a0 + a1) + (a2 + a3);
    r += __shfl_xor_sync(0xffffffffu, r, 1);
    r += __shfl_xor_sync(0xffffffffu, r, 2);
    if (q == 0) bias[b * Hn + h] = r;
}

// ---------------------------------------------------------------------------
// Main: grid (64 s-tiles, 64 b), 256 threads (8 warps: 4M x 2N).
// BM=256, BN=64, BK=64, 8 K-iters. Single-term fp16.
// ---------------------------------------------------------------------------
__global__ __launch_bounds__(256, 2)
void attn_main(const float* __restrict__ SE, const float* __restrict__ DE,
               const __half* __restrict__ Wh,
               const float* __restrict__ v, const float* __restrict__ bias,
               float* __restrict__ scores) {
    extern __shared__ __align__(128) char smem[];
    const uint32_t sb = smem_u32(smem);
    const int tid = threadIdx.x, wid = tid >> 5, lane = tid & 31;
    const int wm = wid & 3, wn = wid >> 2;
    const int b = blockIdx.y;
    const int s0 = blockIdx.x * 64;

    const float* seb = SE + (size_t)b * Hn * Sn;
    const float* deb = DE + (size_t)b * Hn * Sn;

    // X load mapping: 16 floats/thread: row kr (0..63), col chunk cq (x16)
    const int kr = tid >> 2;
    const int cq = (tid & 3) * 16;

    float acc[4][4][4];
#pragma unroll
    for (int mt = 0; mt < 4; mt++)
#pragma unroll
        for (int nt = 0; nt < 4; nt++)
#pragma unroll
            for (int r = 0; r < 4; r++) acc[mt][nt][r] = 0.f;

    // ---- prologue: W stage0 via cp.async, X stage0 via regs ----
    {
        uint32_t s = sb + OFF_W + tid * W_STRIDE;
        const char* gw = (const char*)(Wh + (size_t)tid * 512);
#pragma unroll
        for (int c = 0; c < 8; c++) CP_ASYNC16(s + c * 16, gw + c * 16);
        CP_COMMIT();
        const float* base = seb + (size_t)kr * Sn + s0 + cq;
        float4 x0 = *(const float4*)base;
        float4 x1 = *(const float4*)(base + 4);
        float4 x2 = *(const float4*)(base + 8);
        float4 x3 = *(const float4*)(base + 12);
        uint32_t xoff = (uint32_t)(OFF_X + kr * X_STRIDE + (tid & 3) * 32);
        *(uint4*)(smem + xoff) = cvt8h(x0, x1);
        *(uint4*)(smem + xoff + 16) = cvt8h(x2, x3);
    }

    const uint32_t arow = (uint32_t)((lane & 15) * W_STRIDE + (lane >> 4) * 16);
    const uint32_t xrow = (uint32_t)((lane & 15) * X_STRIDE + (lane >> 4) * 16);

    float4 x0, x1, x2, x3;
    for (int kc = 0; kc < 8; kc++) {
        const int buf = kc & 1;
        CP_WAIT0();
        __syncthreads();

        if (kc < 7) {
            // prefetch W(kc+1) into buf^1
            uint32_t s = sb + (buf ^ 1) * STAGE + OFF_W + tid * W_STRIDE;
            const char* gw = (const char*)(Wh + (size_t)tid * 512 + (kc + 1) * 64);
#pragma unroll
            for (int c = 0; c < 8; c++) CP_ASYNC16(s + c * 16, gw + c * 16);
            CP_COMMIT();
            // load X(kc+1) into regs
            int kn = kc + 1;
            const float* base = ((kn < 4) ? seb : deb)
                              + (size_t)((kn & 3) * 64 + kr) * Sn + s0 + cq;
            x0 = *(const float4*)base;
            x1 = *(const float4*)(base + 4);
            x2 = *(const float4*)(base + 8);
            x3 = *(const float4*)(base + 12);
        }

        // ---- MMA on stage buf: 4 k-sub-chunks of 16 ----
        const uint32_t stage = sb + buf * STAGE;
#pragma unroll
        for (int ks = 0; ks < 4; ks++) {
            uint32_t aH[4][4], bH[4][2];
#pragma unroll
            for (int mt = 0; mt < 4; mt++) {
                uint32_t ad = stage + OFF_W
                    + (uint32_t)((wm * 64 + mt * 16) * W_STRIDE + ks * 32) + arow;
                ldsm_x4(aH[mt], ad);
            }
#pragma unroll
            for (int np = 0; np < 2; np++) {
                uint32_t bd = stage + OFF_X
                    + (uint32_t)(ks * 16 * X_STRIDE + (wn * 32 + np * 16) * 2) + xrow;
                uint32_t t[4];
                ldsm_x4_t(t, bd);
                bH[2 * np][0] = t[0];     bH[2 * np][1] = t[1];
                bH[2 * np + 1][0] = t[2]; bH[2 * np + 1][1] = t[3];
            }
#pragma unroll
            for (int mt = 0; mt < 4; mt++)
#pragma unroll
                for (int nt = 0; nt < 4; nt++)
                    mma_f16(acc[mt][nt], aH[mt], bH[nt]);
        }

        if (kc < 7) {
            uint32_t xoff = (uint32_t)((buf ^ 1) * STAGE + OFF_X
                                       + kr * X_STRIDE + (tid & 3) * 32);
            *(uint4*)(smem + xoff) = cvt8h(x0, x1);
            *(uint4*)(smem + xoff + 16) = cvt8h(x2, x3);
        }
    }

    // ---- epilogue: p = v[h]*tanh(acc+bias[h]); reduce over h ----
    float colsum[4][2];
#pragma unroll
    for (int nt = 0; nt < 4; nt++) { colsum[nt][0] = 0.f; colsum[nt][1] = 0.f; }

#pragma unroll
    for (int mt = 0; mt < 4; mt++) {
        int h0 = wm * 64 + mt * 16 + (lane >> 2);
        float bi0 = bias[b * Hn + h0],     v0 = v[h0];
        float bi1 = bias[b * Hn + h0 + 8], v1 = v[h0 + 8];
#pragma unroll
        for (int nt = 0; nt < 4; nt++) {
            colsum[nt][0] += v0 * tanh_acc(acc[mt][nt][0] + bi0)
                           + v1 * tanh_acc(acc[mt][nt][2] + bi1);
            colsum[nt][1] += v0 * tanh_acc(acc[mt][nt][1] + bi0)
                           + v1 * tanh_acc(acc[mt][nt][3] + bi1);
        }
    }
#pragma unroll
    for (int off = 4; off < 32; off <<= 1)
#pragma unroll
        for (int nt = 0; nt < 4; nt++) {
            colsum[nt][0] += __shfl_xor_sync(0xffffffffu, colsum[nt][0], off);
            colsum[nt][1] += __shfl_xor_sync(0xffffffffu, colsum[nt][1], off);
        }

    __syncthreads();  // stage data no longer needed
    float* spart = (float*)smem;  // [4][64]
    if (lane < 4) {
#pragma unroll
        for (int nt = 0; nt < 4; nt++) {
            spart[wm * 64 + wn * 32 + nt * 8 + lane * 2 + 0] = colsum[nt][0];
            spart[wm * 64 + wn * 32 + nt * 8 + lane * 2 + 1] = colsum[nt][1];
        }
    }
    __syncthreads();
    if (tid < 64) {
        float sc = spart[tid] + spart[64 + tid] + spart[128 + tid] + spart[192 + tid];
        scores[(size_t)b * Sn + s0 + tid] = sc;
    }
}

// ---------------------------------------------------------------------------
__global__ void softmax_kernel(const float* __restrict__ scores,
                               float* __restrict__ out) {
    const int b = blockIdx.x, tid = threadIdx.x;
    const float* row = scores + (size_t)b * Sn;
    float vals[16];
    float mx = -1e30f;
#pragma unroll
    for (int i = 0; i < 16; i++) {
        vals[i] = row[tid + i * 256];
        mx = fmaxf(mx, vals[i]);
    }
#pragma unroll
    for (int off = 16; off; off >>= 1)
        mx = fmaxf(mx, __shfl_xor_sync(0xffffffffu, mx, off));
    __shared__ float sred[8];
    if ((tid & 31) == 0) sred[tid >> 5] = mx;
    __syncthreads();
    float bm = sred[0];
#pragma unroll
    for (int w = 1; w < 8; w++) bm = fmaxf(bm, sred[w]);
    __syncthreads();
    float sum = 0.f;
#pragma unroll
    for (int i = 0; i < 16; i++) { vals[i] = __expf(vals[i] - bm); sum += vals[i]; }
#pragma unroll
    for (int off = 16; off; off >>= 1)
        sum += __shfl_xor_sync(0xffffffffu, sum, off);
    if ((tid & 31) == 0) sred[tid >> 5] = sum;
    __syncthreads();
    float tot = 0.f;
#pragma unroll
    for (int w = 0; w < 8; w++) tot += sred[w];
    float inv = 1.0f / tot;
#pragma unroll
    for (int i = 0; i < 16; i++)
        out[(size_t)b * Sn + tid + i * 256] = vals[i] * inv;
}

// ---------------------------------------------------------------------------
extern "C" void kernel_launch(void* const* d_in, const int* in_sizes, int n_in,
                              void* d_out, int out_size) {
    const float* SE = (const float*)d_in[0];
    const float* DE = (const float*)d_in[1];
    const float* dh = (const float*)d_in[2];
    const float* v  = (const float*)d_in[3];
    const float* W  = (const float*)d_in[4];
    float* out = (float*)d_out;

    __half *wh; float *bias, *scores;
    cudaGetSymbolAddress((void**)&wh, g_Wh);
    cudaGetSymbolAddress((void**)&bias, g_bias);
    cudaGetSymbolAddress((void**)&scores, g_scores);

    cudaFuncSetAttribute(attn_main, cudaFuncAttributeMaxDynamicSharedMemorySize, SMEM_SZ);

    convert_w_kernel<<<128, 256>>>(W, wh);
    bias_kernel<<<Bn, 1024>>>(W, dh, bias);
    attn_main<<<dim3(64, Bn), 256, SMEM_SZ>>>(SE, DE, wh, v, bias, scores);
    softmax_kernel<<<Bn, 256>>>(scores, out);
}

// round 8
// speedup vs baseline: 1.7953x; 1.7953x over previous
#include <cuda_runtime.h>
#include <cuda_fp16.h>
#include <cstdint>

#define Bn 64
#define Hn 256
#define Sn 4096

__device__ __half g_Wh[Hn * 512];
__device__ float g_scores[Bn * Sn];
__device__ float g_bias[Bn * Hn];

// ---- smem geometry (bytes) ----
// BK=32. W: 3 stages of 256 rows x 80B. X: 2 stages of 32 rows x 144B.
#define W_STRIDE 80        // 32 fp16 (64B) + 16B pad -> conflict-free ldmatrix
#define X_STRIDE 144       // 64 fp16 (128B) + 16B pad
#define W_STAGE 20480      // 256*80
#define X_STAGE 4608       // 32*144
#define OFF_X   61440      // 3*W_STAGE
#define SMEM_SZ (OFF_X + 2 * X_STAGE)

// ---------------- PTX helpers (baseline ISA only) ----------------
__device__ __forceinline__ uint32_t smem_u32(const void* p) {
    uint32_t a;
    asm("{ .reg .u64 t; cvta.to.shared.u64 t, %1; cvt.u32.u64 %0, t; }" : "=r"(a) : "l"(p));
    return a;
}
__device__ __forceinline__ void ldsm_x4(uint32_t* r, uint32_t addr) {
    asm volatile("ldmatrix.sync.aligned.m8n8.x4.shared.b16 {%0,%1,%2,%3}, [%4];"
                 : "=r"(r[0]), "=r"(r[1]), "=r"(r[2]), "=r"(r[3]) : "r"(addr));
}
__device__ __forceinline__ void ldsm_x4_t(uint32_t* r, uint32_t addr) {
    asm volatile("ldmatrix.sync.aligned.m8n8.x4.trans.shared.b16 {%0,%1,%2,%3}, [%4];"
                 : "=r"(r[0]), "=r"(r[1]), "=r"(r[2]), "=r"(r[3]) : "r"(addr));
}
__device__ __forceinline__ void mma_f16(float (&d)[4], const uint32_t (&a)[4],
                                        const uint32_t (&b)[2]) {
    asm volatile(
        "mma.sync.aligned.m16n8k16.row.col.f32.f16.f16.f32 "
        "{%0,%1,%2,%3}, {%4,%5,%6,%7}, {%8,%9}, {%0,%1,%2,%3};"
        : "+f"(d[0]), "+f"(d[1]), "+f"(d[2]), "+f"(d[3])
        : "r"(a[0]), "r"(a[1]), "r"(a[2]), "r"(a[3]), "r"(b[0]), "r"(b[1]));
}
#define CP_ASYNC16(s, g) \
    asm volatile("cp.async.cg.shared.global [%0], [%1], 16;" :: "r"(s), "l"(g))
#define CP_COMMIT() asm volatile("cp.async.commit_group;" ::: "memory")
#define CP_WAIT0()  asm volatile("cp.async.wait_group 0;" ::: "memory")
#define CP_WAIT1()  asm volatile("cp.async.wait_group 1;" ::: "memory")

__device__ __forceinline__ float tanh_acc(float x) {
    float z = x * 2.885390082f;           // 2*log2(e)*x
    float e; asm("ex2.approx.f32 %0, %1;" : "=f"(e) : "f"(z));
    float r; asm("rcp.approx.f32 %0, %1;" : "=f"(r) : "f"(e + 1.0f));
    return fmaf(-2.0f, r, 1.0f);          // 1 - 2/(e^{2x}+1)
}

// 8 floats -> 8 fp16 (one uint4)
__device__ __forceinline__ uint4 cvt8h(float4 a, float4 b) {
    __half2 p0 = __floats2half2_rn(a.x, a.y);
    __half2 p1 = __floats2half2_rn(a.z, a.w);
    __half2 p2 = __floats2half2_rn(b.x, b.y);
    __half2 p3 = __floats2half2_rn(b.z, b.w);
    return make_uint4(*(uint32_t*)&p0, *(uint32_t*)&p1,
                      *(uint32_t*)&p2, *(uint32_t*)&p3);
}

// ---------------------------------------------------------------------------
__global__ void convert_w_kernel(const float* __restrict__ W,
                                 __half* __restrict__ wh) {
    int idx = blockIdx.x * 256 + threadIdx.x;  // 0..32767 float4 units
    int h = idx >> 7, c4 = idx & 127;
    float4 w = *(const float4*)(W + (size_t)h * 768 + c4 * 4);
    __half2 h01 = __floats2half2_rn(w.x, w.y);
    __half2 h23 = __floats2half2_rn(w.z, w.w);
    uint2 hh = make_uint2(*(uint32_t*)&h01, *(uint32_t*)&h23);
    *(uint2*)(wh + (size_t)h * 512 + c4 * 4) = hh;
}

// bias[b,h] = W3[h,:] . dh[b,:]  (fp32, exact path)
__global__ void bias_kernel(const float* __restrict__ W,
                            const float* __restrict__ dh,
                            float* __restrict__ bias) {
    int b = blockIdx.x;
    int tid = threadIdx.x;
    __shared__ float sh[Hn];
    if (tid < Hn) sh[tid] = dh[b * Hn + tid];
    __syncthreads();
    int h = tid >> 2, q = tid & 3;
    const float4* Wr = (const float4*)(W + (size_t)h * 768 + 512 + q * 64);
    const float4* sr = (const float4*)(sh + q * 64);
    float a0 = 0.f, a1 = 0.f, a2 = 0.f, a3 = 0.f;
#pragma unroll
    for (int j = 0; j < 16; j++) {
        float4 w4 = __ldg(&Wr[j]); float4 s4 = sr[j];
        a0 = fmaf(w4.x, s4.x, a0); a1 = fmaf(w4.y, s4.y, a1);
        a2 = fmaf(w4.z, s4.z, a2); a3 = fmaf(w4.w, s4.w, a3);
    }
    float r = (a0 + a1) + (a2 + a3);
    r += __shfl_xor_sync(0xffffffffu, r, 1);
    r += __shfl_xor_sync(0xffffffffu, r, 2);
    if (q == 0) bias[b * Hn + h] = r;
}

// ---------------------------------------------------------------------------
// Main: grid (64 s-tiles, 64 b), 256 threads (8 warps: 4M x 2N).
// BM=256, BN=64, BK=32, 16 K-iters. Single-term fp16. 3-stage W pipeline.
// ---------------------------------------------------------------------------
__global__ __launch_bounds__(256, 2)
void attn_main(const float* __restrict__ SE, const float* __restrict__ DE,
               const __half* __restrict__ Wh,
               const float* __restrict__ v, const float* __restrict__ bias,
               float* __restrict__ scores) {
    extern __shared__ __align__(128) char smem[];
    const uint32_t sb = smem_u32(smem);
    const int tid = threadIdx.x, wid = tid >> 5, lane = tid & 31;
    const int wm = wid & 3, wn = wid >> 2;
    const int b = blockIdx.y;
    const int s0 = blockIdx.x * 64;

    const float* seb = SE + (size_t)b * Hn * Sn;
    const float* deb = DE + (size_t)b * Hn * Sn;

    // X load mapping: 8 floats/thread: row kr, col chunk c8
    const int kr = tid >> 3;          // 0..31
    const int c8 = (tid & 7) * 8;     // 0..56

    float acc[4][4][4];
#pragma unroll
    for (int mt = 0; mt < 4; mt++)
#pragma unroll
        for (int nt = 0; nt < 4; nt++)
#pragma unroll
            for (int r = 0; r < 4; r++) acc[mt][nt][r] = 0.f;

    // ---- prologue: W stages 0 and 1 via cp.async, X stage0 via regs ----
    {
        const char* gw = (const char*)(Wh + (size_t)tid * 512);
        uint32_t s0w = sb + tid * W_STRIDE;
#pragma unroll
        for (int c = 0; c < 4; c++) CP_ASYNC16(s0w + c * 16, gw + c * 16);
        CP_COMMIT();
#pragma unroll
        for (int c = 0; c < 4; c++)
            CP_ASYNC16(s0w + W_STAGE + c * 16, gw + 64 + c * 16);
        CP_COMMIT();

        const float* base = seb + (size_t)kr * Sn + s0 + c8;
        float4 xa = *(const float4*)base;
        float4 xb = *(const float4*)(base + 4);
        uint32_t xoff = (uint32_t)(OFF_X + kr * X_STRIDE + (tid & 7) * 16);
        *(uint4*)(smem + xoff) = cvt8h(xa, xb);
    }

    const uint32_t arow = (uint32_t)((lane & 15) * W_STRIDE + (lane >> 4) * 16);
    const uint32_t xrow = (uint32_t)((lane & 15) * X_STRIDE + (lane >> 4) * 16);

    float4 xa, xb;
    for (int kc = 0; kc < 16; kc++) {
        const int bw = kc % 3;        // W stage
        const int bx = kc & 1;        // X stage
        if (kc == 15) { CP_WAIT0(); } else { CP_WAIT1(); }
        __syncthreads();

        if (kc < 14) {
            // prefetch W(kc+2) into stage (kc+2)%3
            uint32_t s = sb + ((kc + 2) % 3) * W_STAGE + tid * W_STRIDE;
            const char* gw = (const char*)(Wh + (size_t)tid * 512 + (kc + 2) * 32);
#pragma unroll
            for (int c = 0; c < 4; c++) CP_ASYNC16(s + c * 16, gw + c * 16);
            CP_COMMIT();
        }
        if (kc < 15) {
            // load X(kc+1) into regs
            int kn = kc + 1;
            const float* base = ((kn < 8) ? seb : deb)
                              + (size_t)((kn & 7) * 32 + kr) * Sn + s0 + c8;
            xa = *(const float4*)base;
            xb = *(const float4*)(base + 4);
        }

        // ---- MMA on W stage bw, X stage bx ----
        const uint32_t wbase = sb + bw * W_STAGE;
        const uint32_t xbase = sb + OFF_X + bx * X_STAGE;
#pragma unroll
        for (int ks = 0; ks < 2; ks++) {
            uint32_t aH[4][4], bH[4][2];
#pragma unroll
            for (int mt = 0; mt < 4; mt++) {
                uint32_t ad = wbase
                    + (uint32_t)((wm * 64 + mt * 16) * W_STRIDE + ks * 32) + arow;
                ldsm_x4(aH[mt], ad);
            }
#pragma unroll
            for (int np = 0; np < 2; np++) {
                uint32_t bd = xbase
                    + (uint32_t)(ks * 16 * X_STRIDE + (wn * 32 + np * 16) * 2) + xrow;
                uint32_t t[4];
                ldsm_x4_t(t, bd);
                bH[2 * np][0] = t[0];     bH[2 * np][1] = t[1];
                bH[2 * np + 1][0] = t[2]; bH[2 * np + 1][1] = t[3];
            }
#pragma unroll
            for (int mt = 0; mt < 4; mt++)
#pragma unroll
                for (int nt = 0; nt < 4; nt++)
                    mma_f16(acc[mt][nt], aH[mt], bH[nt]);
        }

        if (kc < 15) {
            uint32_t xoff = (uint32_t)(OFF_X + (bx ^ 1) * X_STAGE
                                       + kr * X_STRIDE + (tid & 7) * 16);
            *(uint4*)(smem + xoff) = cvt8h(xa, xb);
        }
    }

    // ---- epilogue: p = v[h]*tanh(acc+bias[h]); reduce over h ----
    float colsum[4][2];
#pragma unroll
    for (int nt = 0; nt < 4; nt++) { colsum[nt][0] = 0.f; colsum[nt][1] = 0.f; }

#pragma unroll
    for (int mt = 0; mt < 4; mt++) {
        int h0 = wm * 64 + mt * 16 + (lane >> 2);
        float bi0 = bias[b * Hn + h0],     v0 = v[h0];
        float bi1 = bias[b * Hn + h0 + 8], v1 = v[h0 + 8];
#pragma unroll
        for (int nt = 0; nt < 4; nt++) {
            colsum[nt][0] += v0 * tanh_acc(acc[mt][nt][0] + bi0)
                           + v1 * tanh_acc(acc[mt][nt][2] + bi1);
            colsum[nt][1] += v0 * tanh_acc(acc[mt][nt][1] + bi0)
                           + v1 * tanh_acc(acc[mt][nt][3] + bi1);
        }
    }
#pragma unroll
    for (int off = 4; off < 32; off <<= 1)
#pragma unroll
        for (int nt = 0; nt < 4; nt++) {
            colsum[nt][0] += __shfl_xor_sync(0xffffffffu, colsum[nt][0], off);
            colsum[nt][1] += __shfl_xor_sync(0xffffffffu, colsum[nt][1], off);
        }

    __syncthreads();  // stage data no longer needed
    float* spart = (float*)smem;  // [4][64]
    if (lane < 4) {
#pragma unroll
        for (int nt = 0; nt < 4; nt++) {
            spart[wm * 64 + wn * 32 + nt * 8 + lane * 2 + 0] = colsum[nt][0];
            spart[wm * 64 + wn * 32 + nt * 8 + lane * 2 + 1] = colsum[nt][1];
        }
    }
    __syncthreads();
    if (tid < 64) {
        float sc = spart[tid] + spart[64 + tid] + spart[128 + tid] + spart[192 + tid];
        scores[(size_t)b * Sn + s0 + tid] = sc;
    }
}

// ---------------------------------------------------------------------------
__global__ void softmax_kernel(const float* __restrict__ scores,
                               float* __restrict__ out) {
    const int b = blockIdx.x, tid = threadIdx.x;
    const float* row = scores + (size_t)b * Sn;
    float vals[16];
    float mx = -1e30f;
#pragma unroll
    for (int i = 0; i < 16; i++) {
        vals[i] = row[tid + i * 256];
        mx = fmaxf(mx, vals[i]);
    }
#pragma unroll
    for (int off = 16; off; off >>= 1)
        mx = fmaxf(mx, __shfl_xor_sync(0xffffffffu, mx, off));
    __shared__ float sred[8];
    if ((tid & 31) == 0) sred[tid >> 5] = mx;
    __syncthreads();
    float bm = sred[0];
#pragma unroll
    for (int w = 1; w < 8; w++) bm = fmaxf(bm, sred[w]);
    __syncthreads();
    float sum = 0.f;
#pragma unroll
    for (int i = 0; i < 16; i++) { vals[i] = __expf(vals[i] - bm); sum += vals[i]; }
#pragma unroll
    for (int off = 16; off; off >>= 1)
        sum += __shfl_xor_sync(0xffffffffu, sum, off);
    if ((tid & 31) == 0) sred[tid >> 5] = sum;
    __syncthreads();
    float tot = 0.f;
#pragma unroll
    for (int w = 0; w < 8; w++) tot += sred[w];
    float inv = 1.0f / tot;
#pragma unroll
    for (int i = 0; i < 16; i++)
        out[(size_t)b * Sn + tid + i * 256] = vals[i] * inv;
}

// ---------------------------------------------------------------------------
extern "C" void kernel_launch(void* const* d_in, const int* in_sizes, int n_in,
                              void* d_out, int out_size) {
    const float* SE = (const float*)d_in[0];
    const float* DE = (const float*)d_in[1];
    const float* dh = (const float*)d_in[2];
    const float* v  = (const float*)d_in[3];
    const float* W  = (const float*)d_in[4];
    float* out = (float*)d_out;

    __half *wh; float *bias, *scores;
    cudaGetSymbolAddress((void**)&wh, g_Wh);
    cudaGetSymbolAddress((void**)&bias, g_bias);
    cudaGetSymbolAddress((void**)&scores, g_scores);

    cudaFuncSetAttribute(attn_main, cudaFuncAttributeMaxDynamicSharedMemorySize, SMEM_SZ);

    convert_w_kernel<<<128, 256>>>(W, wh);
    bias_kernel<<<Bn, 1024>>>(W, dh, bias);
    attn_main<<<dim3(64, Bn), 256, SMEM_SZ>>>(SE, DE, wh, v, bias, scores);
    softmax_kernel<<<Bn, 256>>>(scores, out);
}

// round 9
// speedup vs baseline: 2.3665x; 1.3181x over previous
#include <cuda_runtime.h>
#include <cuda_fp16.h>
#include <cstdint>

#define Bn 64
#define Hn 256
#define Sn 4096

__device__ __half g_Wh[Hn * 512];
__device__ float g_scores[Bn * Sn];
__device__ float g_bias[Bn * Hn];

// ---- smem geometry (bytes) ----
// BK=32, BN=128. W: 3 stages 256 x 80B. X: 2 stages 32 x 272B.
#define W_STRIDE 80        // 32 fp16 (64B) + 16B pad
#define X_STRIDE 272       // 128 fp16 (256B) + 16B pad
#define W_STAGE 20480      // 256*80
#define X_STAGE 8704       // 32*272
#define OFF_X   61440      // 3*W_STAGE
#define SMEM_SZ (OFF_X + 2 * X_STAGE)

// ---------------- PTX helpers (baseline ISA only) ----------------
__device__ __forceinline__ uint32_t smem_u32(const void* p) {
    uint32_t a;
    asm("{ .reg .u64 t; cvta.to.shared.u64 t, %1; cvt.u32.u64 %0, t; }" : "=r"(a) : "l"(p));
    return a;
}
__device__ __forceinline__ void ldsm_x4(uint32_t* r, uint32_t addr) {
    asm volatile("ldmatrix.sync.aligned.m8n8.x4.shared.b16 {%0,%1,%2,%3}, [%4];"
                 : "=r"(r[0]), "=r"(r[1]), "=r"(r[2]), "=r"(r[3]) : "r"(addr));
}
__device__ __forceinline__ void ldsm_x4_t(uint32_t* r, uint32_t addr) {
    asm volatile("ldmatrix.sync.aligned.m8n8.x4.trans.shared.b16 {%0,%1,%2,%3}, [%4];"
                 : "=r"(r[0]), "=r"(r[1]), "=r"(r[2]), "=r"(r[3]) : "r"(addr));
}
__device__ __forceinline__ void mma_f16(float (&d)[4], const uint32_t (&a)[4],
                                        const uint32_t (&b)[2]) {
    asm volatile(
        "mma.sync.aligned.m16n8k16.row.col.f32.f16.f16.f32 "
        "{%0,%1,%2,%3}, {%4,%5,%6,%7}, {%8,%9}, {%0,%1,%2,%3};"
        : "+f"(d[0]), "+f"(d[1]), "+f"(d[2]), "+f"(d[3])
        : "r"(a[0]), "r"(a[1]), "r"(a[2]), "r"(a[3]), "r"(b[0]), "r"(b[1]));
}
#define CP_ASYNC16(s, g) \
    asm volatile("cp.async.cg.shared.global [%0], [%1], 16;" :: "r"(s), "l"(g))
#define CP_COMMIT() asm volatile("cp.async.commit_group;" ::: "memory")
#define CP_WAIT0()  asm volatile("cp.async.wait_group 0;" ::: "memory")
#define CP_WAIT1()  asm volatile("cp.async.wait_group 1;" ::: "memory")

__device__ __forceinline__ float tanh_acc(float x) {
    float z = x * 2.885390082f;           // 2*log2(e)*x
    float e; asm("ex2.approx.f32 %0, %1;" : "=f"(e) : "f"(z));
    float r; asm("rcp.approx.f32 %0, %1;" : "=f"(r) : "f"(e + 1.0f));
    return fmaf(-2.0f, r, 1.0f);          // 1 - 2/(e^{2x}+1)
}

// 8 floats -> 8 fp16 (one uint4)
__device__ __forceinline__ uint4 cvt8h(float4 a, float4 b) {
    __half2 p0 = __floats2half2_rn(a.x, a.y);
    __half2 p1 = __floats2half2_rn(a.z, a.w);
    __half2 p2 = __floats2half2_rn(b.x, b.y);
    __half2 p3 = __floats2half2_rn(b.z, b.w);
    return make_uint4(*(uint32_t*)&p0, *(uint32_t*)&p1,
                      *(uint32_t*)&p2, *(uint32_t*)&p3);
}

// ---------------------------------------------------------------------------
// Merged prep kernel: blocks 0..31 convert W[:, :512] -> fp16;
// blocks 32..95 compute bias[b,h] = W3[h,:] . dh[b,:]. 1024 threads.
// ---------------------------------------------------------------------------
__global__ void prep_kernel(const float* __restrict__ W,
                            const float* __restrict__ dh,
                            __half* __restrict__ wh,
                            float* __restrict__ bias) {
    int tid = threadIdx.x;
    if (blockIdx.x < 32) {
        int idx = blockIdx.x * 1024 + tid;  // 0..32767 float4 units
        int h = idx >> 7, c4 = idx & 127;
        float4 w = *(const float4*)(W + (size_t)h * 768 + c4 * 4);
        __half2 h01 = __floats2half2_rn(w.x, w.y);
        __half2 h23 = __floats2half2_rn(w.z, w.w);
        uint2 hh = make_uint2(*(uint32_t*)&h01, *(uint32_t*)&h23);
        *(uint2*)(wh + (size_t)h * 512 + c4 * 4) = hh;
    } else {
        int b = blockIdx.x - 32;
        __shared__ float sh[Hn];
        if (tid < Hn) sh[tid] = dh[b * Hn + tid];
        __syncthreads();
        int h = tid >> 2, q = tid & 3;
        const float4* Wr = (const float4*)(W + (size_t)h * 768 + 512 + q * 64);
        const float4* sr = (const float4*)(sh + q * 64);
        float a0 = 0.f, a1 = 0.f, a2 = 0.f, a3 = 0.f;
#pragma unroll
        for (int j = 0; j < 16; j++) {
            float4 w4 = __ldg(&Wr[j]); float4 s4 = sr[j];
            a0 = fmaf(w4.x, s4.x, a0); a1 = fmaf(w4.y, s4.y, a1);
            a2 = fmaf(w4.z, s4.z, a2); a3 = fmaf(w4.w, s4.w, a3);
        }
        float r = (a0 + a1) + (a2 + a3);
        r += __shfl_xor_sync(0xffffffffu, r, 1);
        r += __shfl_xor_sync(0xffffffffu, r, 2);
        if (q == 0) bias[b * Hn + h] = r;
    }
}

// ---------------------------------------------------------------------------
// Main: grid (32 s-tiles, 64 b), 512 threads (16 warps: 4M x 4N).
// BM=256, BN=128, BK=32, 16 K-iters. Single-term fp16. 3-stage W pipeline.
// ---------------------------------------------------------------------------
__global__ __launch_bounds__(512, 1)
void attn_main(const float* __restrict__ SE, const float* __restrict__ DE,
               const __half* __restrict__ Wh,
               const float* __restrict__ v, const float* __restrict__ bias,
               float* __restrict__ scores) {
    extern __shared__ __align__(128) char smem[];
    const uint32_t sb = smem_u32(smem);
    const int tid = threadIdx.x, wid = tid >> 5, lane = tid & 31;
    const int wm = wid & 3, wn = wid >> 2;
    const int b = blockIdx.y;
    const int s0 = blockIdx.x * 128;

    const float* seb = SE + (size_t)b * Hn * Sn;
    const float* deb = DE + (size_t)b * Hn * Sn;

    // X load mapping: 8 floats/thread: row kr (0..31), col chunk c8 (0..120)
    const int kr = tid >> 4;
    const int c8 = (tid & 15) * 8;
    // W load mapping: 2 cp.async16/thread: row tid>>1, halves
    const int wrow = tid >> 1;
    const int wcol = (tid & 1) * 32;  // bytes

    float acc[4][4][4];
#pragma unroll
    for (int mt = 0; mt < 4; mt++)
#pragma unroll
        for (int nt = 0; nt < 4; nt++)
#pragma unroll
            for (int r = 0; r < 4; r++) acc[mt][nt][r] = 0.f;

    // ---- prologue: W stages 0,1 via cp.async, X stage0 via regs ----
    {
        const char* gw = (const char*)(Wh + (size_t)wrow * 512) + wcol;
        uint32_t sw = sb + wrow * W_STRIDE + wcol;
        CP_ASYNC16(sw, gw);
        CP_ASYNC16(sw + 16, gw + 16);
        CP_COMMIT();
        CP_ASYNC16(sw + W_STAGE, gw + 64);
        CP_ASYNC16(sw + W_STAGE + 16, gw + 64 + 16);
        CP_COMMIT();

        const float* base = seb + (size_t)kr * Sn + s0 + c8;
        float4 xa = *(const float4*)base;
        float4 xb = *(const float4*)(base + 4);
        uint32_t xoff = (uint32_t)(OFF_X + kr * X_STRIDE + (tid & 15) * 16);
        *(uint4*)(smem + xoff) = cvt8h(xa, xb);
    }

    const uint32_t arow = (uint32_t)((lane & 15) * W_STRIDE + (lane >> 4) * 16);
    const uint32_t xrow = (uint32_t)((lane & 15) * X_STRIDE + (lane >> 4) * 16);

    float4 xa, xb;
    for (int kc = 0; kc < 16; kc++) {
        const int bw = kc % 3;        // W stage
        const int bx = kc & 1;        // X stage
        if (kc == 15) { CP_WAIT0(); } else { CP_WAIT1(); }
        __syncthreads();

        if (kc < 14) {
            // prefetch W(kc+2) into stage (kc+2)%3
            uint32_t s = sb + ((kc + 2) % 3) * W_STAGE + wrow * W_STRIDE + wcol;
            const char* gw = (const char*)(Wh + (size_t)wrow * 512 + (kc + 2) * 32) + wcol;
            CP_ASYNC16(s, gw);
            CP_ASYNC16(s + 16, gw + 16);
            CP_COMMIT();
        }
        if (kc < 15) {
            // load X(kc+1) into regs
            int kn = kc + 1;
            const float* base = ((kn < 8) ? seb : deb)
                              + (size_t)((kn & 7) * 32 + kr) * Sn + s0 + c8;
            xa = *(const float4*)base;
            xb = *(const float4*)(base + 4);
        }

        // ---- MMA on W stage bw, X stage bx ----
        const uint32_t wbase = sb + bw * W_STAGE;
        const uint32_t xbase = sb + OFF_X + bx * X_STAGE;
#pragma unroll
        for (int ks = 0; ks < 2; ks++) {
            uint32_t aH[4][4], bH[4][2];
#pragma unroll
            for (int mt = 0; mt < 4; mt++) {
                uint32_t ad = wbase
                    + (uint32_t)((wm * 64 + mt * 16) * W_STRIDE + ks * 32) + arow;
                ldsm_x4(aH[mt], ad);
            }
#pragma unroll
            for (int np = 0; np < 2; np++) {
                uint32_t bd = xbase
                    + (uint32_t)(ks * 16 * X_STRIDE + (wn * 32 + np * 16) * 2) + xrow;
                uint32_t t[4];
                ldsm_x4_t(t, bd);
                bH[2 * np][0] = t[0];     bH[2 * np][1] = t[1];
                bH[2 * np + 1][0] = t[2]; bH[2 * np + 1][1] = t[3];
            }
#pragma unroll
            for (int mt = 0; mt < 4; mt++)
#pragma unroll
                for (int nt = 0; nt < 4; nt++)
                    mma_f16(acc[mt][nt], aH[mt], bH[nt]);
        }

        if (kc < 15) {
            uint32_t xoff = (uint32_t)(OFF_X + (bx ^ 1) * X_STAGE
                                       + kr * X_STRIDE + (tid & 15) * 16);
            *(uint4*)(smem + xoff) = cvt8h(xa, xb);
        }
    }

    // ---- epilogue: p = v[h]*tanh(acc+bias[h]); reduce over h ----
    float colsum[4][2];
#pragma unroll
    for (int nt = 0; nt < 4; nt++) { colsum[nt][0] = 0.f; colsum[nt][1] = 0.f; }

#pragma unroll
    for (int mt = 0; mt < 4; mt++) {
        int h0 = wm * 64 + mt * 16 + (lane >> 2);
        float bi0 = bias[b * Hn + h0],     v0 = v[h0];
        float bi1 = bias[b * Hn + h0 + 8], v1 = v[h0 + 8];
#pragma unroll
        for (int nt = 0; nt < 4; nt++) {
            colsum[nt][0] += v0 * tanh_acc(acc[mt][nt][0] + bi0)
                           + v1 * tanh_acc(acc[mt][nt][2] + bi1);
            colsum[nt][1] += v0 * tanh_acc(acc[mt][nt][1] + bi0)
                           + v1 * tanh_acc(acc[mt][nt][3] + bi1);
        }
    }
#pragma unroll
    for (int off = 4; off < 32; off <<= 1)
#pragma unroll
        for (int nt = 0; nt < 4; nt++) {
            colsum[nt][0] += __shfl_xor_sync(0xffffffffu, colsum[nt][0], off);
            colsum[nt][1] += __shfl_xor_sync(0xffffffffu, colsum[nt][1], off);
        }

    __syncthreads();  // stage data no longer needed
    float* spart = (float*)smem;  // [4][128]
    if (lane < 4) {
#pragma unroll
        for (int nt = 0; nt < 4; nt++) {
            spart[wm * 128 + wn * 32 + nt * 8 + lane * 2 + 0] = colsum[nt][0];
            spart[wm * 128 + wn * 32 + nt * 8 + lane * 2 + 1] = colsum[nt][1];
        }
    }
    __syncthreads();
    if (tid < 128) {
        float sc = spart[tid] + spart[128 + tid] + spart[256 + tid] + spart[384 + tid];
        scores[(size_t)b * Sn + s0 + tid] = sc;
    }
}

// ---------------------------------------------------------------------------
__global__ void softmax_kernel(const float* __restrict__ scores,
                               float* __restrict__ out) {
    const int b = blockIdx.x, tid = threadIdx.x;
    const float* row = scores + (size_t)b * Sn;
    float vals[16];
    float mx = -1e30f;
#pragma unroll
    for (int i = 0; i < 16; i++) {
        vals[i] = row[tid + i * 256];
        mx = fmaxf(mx, vals[i]);
    }
#pragma unroll
    for (int off = 16; off; off >>= 1)
        mx = fmaxf(mx, __shfl_xor_sync(0xffffffffu, mx, off));
    __shared__ float sred[8];
    if ((tid & 31) == 0) sred[tid >> 5] = mx;
    __syncthreads();
    float bm = sred[0];
#pragma unroll
    for (int w = 1; w < 8; w++) bm = fmaxf(bm, sred[w]);
    __syncthreads();
    float sum = 0.f;
#pragma unroll
    for (int i = 0; i < 16; i++) { vals[i] = __expf(vals[i] - bm); sum += vals[i]; }
#pragma unroll
    for (int off = 16; off; off >>= 1)
        sum += __shfl_xor_sync(0xffffffffu, sum, off);
    if ((tid & 31) == 0) sred[tid >> 5] = sum;
    __syncthreads();
    float tot = 0.f;
#pragma unroll
    for (int w = 0; w < 8; w++) tot += sred[w];
    float inv = 1.0f / tot;
#pragma unroll
    for (int i = 0; i < 16; i++)
        out[(size_t)b * Sn + tid + i * 256] = vals[i] * inv;
}

// ---------------------------------------------------------------------------
extern "C" void kernel_launch(void* const* d_in, const int* in_sizes, int n_in,
                              void* d_out, int out_size) {
    const float* SE = (const float*)d_in[0];
    const float* DE = (const float*)d_in[1];
    const float* dh = (const float*)d_in[2];
    const float* v  = (const float*)d_in[3];
    const float* W  = (const float*)d_in[4];
    float* out = (float*)d_out;

    __half *wh; float *bias, *scores;
    cudaGetSymbolAddress((void**)&wh, g_Wh);
    cudaGetSymbolAddress((void**)&bias, g_bias);
    cudaGetSymbolAddress((void**)&scores, g_scores);

    cudaFuncSetAttribute(attn_main, cudaFuncAttributeMaxDynamicSharedMemorySize, SMEM_SZ);

    prep_kernel<<<96, 1024>>>(W, dh, wh, bias);
    attn_main<<<dim3(32, Bn), 512, SMEM_SZ>>>(SE, DE, wh, v, bias, scores);
    softmax_kernel<<<Bn, 256>>>(scores, out);
}

// round 10
// speedup vs baseline: 2.4503x; 1.0354x over previous
#include <cuda_runtime.h>
#include <cuda_fp16.h>
#include <cstdint>

#define Bn 64
#define Hn 256
#define Sn 4096

__device__ __half g_Wh[Hn * 512];
__device__ float g_scores[Bn * Sn];
__device__ float g_bias[Bn * Hn];

// ---- smem geometry (bytes) ----
// BK=32, BN=128. W: 3 stages 256 x 80B. X: 2 stages 32 x 272B.
#define W_STRIDE 80        // 32 fp16 (64B) + 16B pad
#define X_STRIDE 272       // 128 fp16 (256B) + 16B pad
#define W_STAGE 20480      // 256*80
#define X_STAGE 8704       // 32*272
#define OFF_X   61440      // 3*W_STAGE
#define SMEM_SZ (OFF_X + 2 * X_STAGE)

// ---------------- PTX helpers (baseline ISA only) ----------------
__device__ __forceinline__ uint32_t smem_u32(const void* p) {
    uint32_t a;
    asm("{ .reg .u64 t; cvta.to.shared.u64 t, %1; cvt.u32.u64 %0, t; }" : "=r"(a) : "l"(p));
    return a;
}
__device__ __forceinline__ void ldsm_x4(uint32_t* r, uint32_t addr) {
    asm volatile("ldmatrix.sync.aligned.m8n8.x4.shared.b16 {%0,%1,%2,%3}, [%4];"
                 : "=r"(r[0]), "=r"(r[1]), "=r"(r[2]), "=r"(r[3]) : "r"(addr));
}
__device__ __forceinline__ void ldsm_x4_t(uint32_t* r, uint32_t addr) {
    asm volatile("ldmatrix.sync.aligned.m8n8.x4.trans.shared.b16 {%0,%1,%2,%3}, [%4];"
                 : "=r"(r[0]), "=r"(r[1]), "=r"(r[2]), "=r"(r[3]) : "r"(addr));
}
__device__ __forceinline__ void mma_f16(float (&d)[4], const uint32_t (&a)[4],
                                        const uint32_t (&b)[2]) {
    asm volatile(
        "mma.sync.aligned.m16n8k16.row.col.f32.f16.f16.f32 "
        "{%0,%1,%2,%3}, {%4,%5,%6,%7}, {%8,%9}, {%0,%1,%2,%3};"
        : "+f"(d[0]), "+f"(d[1]), "+f"(d[2]), "+f"(d[3])
        : "r"(a[0]), "r"(a[1]), "r"(a[2]), "r"(a[3]), "r"(b[0]), "r"(b[1]));
}
#define CP_ASYNC16(s, g) \
    asm volatile("cp.async.cg.shared.global [%0], [%1], 16;" :: "r"(s), "l"(g))
#define CP_COMMIT() asm volatile("cp.async.commit_group;" ::: "memory")
#define CP_WAIT0()  asm volatile("cp.async.wait_group 0;" ::: "memory")
#define CP_WAIT1()  asm volatile("cp.async.wait_group 1;" ::: "memory")

__device__ __forceinline__ float tanh_acc(float x) {
    float z = x * 2.885390082f;           // 2*log2(e)*x
    float e; asm("ex2.approx.f32 %0, %1;" : "=f"(e) : "f"(z));
    float r; asm("rcp.approx.f32 %0, %1;" : "=f"(r) : "f"(e + 1.0f));
    return fmaf(-2.0f, r, 1.0f);          // 1 - 2/(e^{2x}+1)
}

// 8 floats -> 8 fp16 (one uint4)
__device__ __forceinline__ uint4 cvt8h(float4 a, float4 b) {
    __half2 p0 = __floats2half2_rn(a.x, a.y);
    __half2 p1 = __floats2half2_rn(a.z, a.w);
    __half2 p2 = __floats2half2_rn(b.x, b.y);
    __half2 p3 = __floats2half2_rn(b.z, b.w);
    return make_uint4(*(uint32_t*)&p0, *(uint32_t*)&p1,
                      *(uint32_t*)&p2, *(uint32_t*)&p3);
}

// ---------------------------------------------------------------------------
// Prep kernel, 2176 blocks x 256 threads:
//  blocks 0..127: convert W[:, :512] -> fp16 (coalesced float4 per thread)
//  blocks 128..2175: bias. One warp per (b, h): coalesced row dot product.
// ---------------------------------------------------------------------------
__global__ void prep_kernel(const float* __restrict__ W,
                            const float* __restrict__ dh,
                            __half* __restrict__ wh,
                            float* __restrict__ bias) {
    int tid = threadIdx.x;
    if (blockIdx.x < 128) {
        int idx = blockIdx.x * 256 + tid;  // 0..32767 float4 units
        int h = idx >> 7, c4 = idx & 127;
        float4 w = *(const float4*)(W + (size_t)h * 768 + c4 * 4);
        __half2 h01 = __floats2half2_rn(w.x, w.y);
        __half2 h23 = __floats2half2_rn(w.z, w.w);
        uint2 hh = make_uint2(*(uint32_t*)&h01, *(uint32_t*)&h23);
        *(uint2*)(wh + (size_t)h * 512 + c4 * 4) = hh;
    } else {
        int g = blockIdx.x - 128;          // 0..2047
        int b = g >> 5;                    // batch
        int wid = tid >> 5, lane = tid & 31;
        int h = (g & 31) * 8 + wid;        // row of W3
        // coalesced: lane reads W3[h, lane*4..] and W3[h, 128+lane*4..]
        const float4* wr = (const float4*)(W + (size_t)h * 768 + 512);
        const float4* dr = (const float4*)(dh + (size_t)b * Hn);
        float4 w0 = __ldg(&wr[lane]);
        float4 w1 = __ldg(&wr[32 + lane]);
        float4 d0 = __ldg(&dr[lane]);
        float4 d1 = __ldg(&dr[32 + lane]);
        float s = w0.x * d0.x + w0.y * d0.y + w0.z * d0.z + w0.w * d0.w
                + w1.x * d1.x + w1.y * d1.y + w1.z * d1.z + w1.w * d1.w;
#pragma unroll
        for (int off = 16; off; off >>= 1)
            s += __shfl_xor_sync(0xffffffffu, s, off);
        if (lane == 0) bias[b * Hn + h] = s;
    }
}

// ---------------------------------------------------------------------------
// Main: grid (32 s-tiles, 64 b), 512 threads (16 warps: 4M x 4N).
// BM=256, BN=128, BK=32, 16 K-iters. Single-term fp16. 3-stage W pipeline.
// ---------------------------------------------------------------------------
__global__ __launch_bounds__(512, 1)
void attn_main(const float* __restrict__ SE, const float* __restrict__ DE,
               const __half* __restrict__ Wh,
               const float* __restrict__ v, const float* __restrict__ bias,
               float* __restrict__ scores) {
    extern __shared__ __align__(128) char smem[];
    const uint32_t sb = smem_u32(smem);
    const int tid = threadIdx.x, wid = tid >> 5, lane = tid & 31;
    const int wm = wid & 3, wn = wid >> 2;
    const int b = blockIdx.y;
    const int s0 = blockIdx.x * 128;

    const float* seb = SE + (size_t)b * Hn * Sn;
    const float* deb = DE + (size_t)b * Hn * Sn;

    // X load mapping: 8 floats/thread: row kr (0..31), col chunk c8 (0..120)
    const int kr = tid >> 4;
    const int c8 = (tid & 15) * 8;
    // W load mapping: 2 cp.async16/thread: row tid>>1, halves
    const int wrow = tid >> 1;
    const int wcol = (tid & 1) * 32;  // bytes

    float acc[4][4][4];
#pragma unroll
    for (int mt = 0; mt < 4; mt++)
#pragma unroll
        for (int nt = 0; nt < 4; nt++)
#pragma unroll
            for (int r = 0; r < 4; r++) acc[mt][nt][r] = 0.f;

    // ---- prologue: W stages 0,1 via cp.async, X stage0 via regs ----
    {
        const char* gw = (const char*)(Wh + (size_t)wrow * 512) + wcol;
        uint32_t sw = sb + wrow * W_STRIDE + wcol;
        CP_ASYNC16(sw, gw);
        CP_ASYNC16(sw + 16, gw + 16);
        CP_COMMIT();
        CP_ASYNC16(sw + W_STAGE, gw + 64);
        CP_ASYNC16(sw + W_STAGE + 16, gw + 64 + 16);
        CP_COMMIT();

        const float* base = seb + (size_t)kr * Sn + s0 + c8;
        float4 xa = *(const float4*)base;
        float4 xb = *(const float4*)(base + 4);
        uint32_t xoff = (uint32_t)(OFF_X + kr * X_STRIDE + (tid & 15) * 16);
        *(uint4*)(smem + xoff) = cvt8h(xa, xb);
    }

    const uint32_t arow = (uint32_t)((lane & 15) * W_STRIDE + (lane >> 4) * 16);
    const uint32_t xrow = (uint32_t)((lane & 15) * X_STRIDE + (lane >> 4) * 16);

    float4 xa, xb;
    for (int kc = 0; kc < 16; kc++) {
        const int bw = kc % 3;        // W stage
        const int bx = kc & 1;        // X stage
        if (kc == 15) { CP_WAIT0(); } else { CP_WAIT1(); }
        __syncthreads();

        if (kc < 14) {
            // prefetch W(kc+2) into stage (kc+2)%3
            uint32_t s = sb + ((kc + 2) % 3) * W_STAGE + wrow * W_STRIDE + wcol;
            const char* gw = (const char*)(Wh + (size_t)wrow * 512 + (kc + 2) * 32) + wcol;
            CP_ASYNC16(s, gw);
            CP_ASYNC16(s + 16, gw + 16);
            CP_COMMIT();
        }
        if (kc < 15) {
            // load X(kc+1) into regs
            int kn = kc + 1;
            const float* base = ((kn < 8) ? seb : deb)
                              + (size_t)((kn & 7) * 32 + kr) * Sn + s0 + c8;
            xa = *(const float4*)base;
            xb = *(const float4*)(base + 4);
        }

        // ---- MMA on W stage bw, X stage bx ----
        const uint32_t wbase = sb + bw * W_STAGE;
        const uint32_t xbase = sb + OFF_X + bx * X_STAGE;
#pragma unroll
        for (int ks = 0; ks < 2; ks++) {
            uint32_t aH[4][4], bH[4][2];
#pragma unroll
            for (int mt = 0; mt < 4; mt++) {
                uint32_t ad = wbase
                    + (uint32_t)((wm * 64 + mt * 16) * W_STRIDE + ks * 32) + arow;
                ldsm_x4(aH[mt], ad);
            }
#pragma unroll
            for (int np = 0; np < 2; np++) {
                uint32_t bd = xbase
                    + (uint32_t)(ks * 16 * X_STRIDE + (wn * 32 + np * 16) * 2) + xrow;
                uint32_t t[4];
                ldsm_x4_t(t, bd);
                bH[2 * np][0] = t[0];     bH[2 * np][1] = t[1];
                bH[2 * np + 1][0] = t[2]; bH[2 * np + 1][1] = t[3];
            }
#pragma unroll
            for (int mt = 0; mt < 4; mt++)
#pragma unroll
                for (int nt = 0; nt < 4; nt++)
                    mma_f16(acc[mt][nt], aH[mt], bH[nt]);
        }

        if (kc < 15) {
            uint32_t xoff = (uint32_t)(OFF_X + (bx ^ 1) * X_STAGE
                                       + kr * X_STRIDE + (tid & 15) * 16);
            *(uint4*)(smem + xoff) = cvt8h(xa, xb);
        }
    }

    // ---- epilogue: p = v[h]*tanh(acc+bias[h]); reduce over h ----
    float colsum[4][2];
#pragma unroll
    for (int nt = 0; nt < 4; nt++) { colsum[nt][0] = 0.f; colsum[nt][1] = 0.f; }

#pragma unroll
    for (int mt = 0; mt < 4; mt++) {
        int h0 = wm * 64 + mt * 16 + (lane >> 2);
        float bi0 = bias[b * Hn + h0],     v0 = v[h0];
        float bi1 = bias[b * Hn + h0 + 8], v1 = v[h0 + 8];
#pragma unroll
        for (int nt = 0; nt < 4; nt++) {
            colsum[nt][0] += v0 * tanh_acc(acc[mt][nt][0] + bi0)
                           + v1 * tanh_acc(acc[mt][nt][2] + bi1);
            colsum[nt][1] += v0 * tanh_acc(acc[mt][nt][1] + bi0)
                           + v1 * tanh_acc(acc[mt][nt][3] + bi1);
        }
    }
#pragma unroll
    for (int off = 4; off < 32; off <<= 1)
#pragma unroll
        for (int nt = 0; nt < 4; nt++) {
            colsum[nt][0] += __shfl_xor_sync(0xffffffffu, colsum[nt][0], off);
            colsum[nt][1] += __shfl_xor_sync(0xffffffffu, colsum[nt][1], off);
        }

    __syncthreads();  // stage data no longer needed
    float* spart = (float*)smem;  // [4][128]
    if (lane < 4) {
#pragma unroll
        for (int nt = 0; nt < 4; nt++) {
            spart[wm * 128 + wn * 32 + nt * 8 + lane * 2 + 0] = colsum[nt][0];
            spart[wm * 128 + wn * 32 + nt * 8 + lane * 2 + 1] = colsum[nt][1];
        }
    }
    __syncthreads();
    if (tid < 128) {
        float sc = spart[tid] + spart[128 + tid] + spart[256 + tid] + spart[384 + tid];
        scores[(size_t)b * Sn + s0 + tid] = sc;
    }
}

// ---------------------------------------------------------------------------
__global__ void softmax_kernel(const float* __restrict__ scores,
                               float* __restrict__ out) {
    const int b = blockIdx.x, tid = threadIdx.x;
    const float* row = scores + (size_t)b * Sn;
    float vals[16];
    float mx = -1e30f;
#pragma unroll
    for (int i = 0; i < 16; i++) {
        vals[i] = row[tid + i * 256];
        mx = fmaxf(mx, vals[i]);
    }
#pragma unroll
    for (int off = 16; off; off >>= 1)
        mx = fmaxf(mx, __shfl_xor_sync(0xffffffffu, mx, off));
    __shared__ float sred[8];
    if ((tid & 31) == 0) sred[tid >> 5] = mx;
    __syncthreads();
    float bm = sred[0];
#pragma unroll
    for (int w = 1; w < 8; w++) bm = fmaxf(bm, sred[w]);
    __syncthreads();
    float sum = 0.f;
#pragma unroll
    for (int i = 0; i < 16; i++) { vals[i] = __expf(vals[i] - bm); sum += vals[i]; }
#pragma unroll
    for (int off = 16; off; off >>= 1)
        sum += __shfl_xor_sync(0xffffffffu, sum, off);
    if ((tid & 31) == 0) sred[tid >> 5] = sum;
    __syncthreads();
    float tot = 0.f;
#pragma unroll
    for (int w = 0; w < 8; w++) tot += sred[w];
    float inv = 1.0f / tot;
#pragma unroll
    for (int i = 0; i < 16; i++)
        out[(size_t)b * Sn + tid + i * 256] = vals[i] * inv;
}

// ---------------------------------------------------------------------------
extern "C" void kernel_launch(void* const* d_in, const int* in_sizes, int n_in,
                              void* d_out, int out_size) {
    const float* SE = (const float*)d_in[0];
    const float* DE = (const float*)d_in[1];
    const float* dh = (const float*)d_in[2];
    const float* v  = (const float*)d_in[3];
    const float* W  = (const float*)d_in[4];
    float* out = (float*)d_out;

    __half *wh; float *bias, *scores;
    cudaGetSymbolAddress((void**)&wh, g_Wh);
    cudaGetSymbolAddress((void**)&bias, g_bias);
    cudaGetSymbolAddress((void**)&scores, g_scores);

    cudaFuncSetAttribute(attn_main, cudaFuncAttributeMaxDynamicSharedMemorySize, SMEM_SZ);

    prep_kernel<<<2176, 256>>>(W, dh, wh, bias);
    attn_main<<<dim3(32, Bn), 512, SMEM_SZ>>>(SE, DE, wh, v, bias, scores);
    softmax_kernel<<<Bn, 256>>>(scores, out);
}